// round 12
// baseline (speedup 1.0000x reference)
#include <cuda_runtime.h>

#define BB 128
#define PP 34125
#define OO 16
#define CC 21
#define NEGPOS 3
#define VAR0 0.1f
#define VAR1 0.2f
#define THRESH 0.35f
#define TM 16                // best-prior tiles per batch
#define TC 16                // CE tiles per batch
#define NTILES ((PP + 31) / 32)          // 1067
#define TPC ((NTILES + TC - 1) / TC)     // 67 warp-tiles per CE CTA

// scratch (device globals; every word read is written earlier in the same call)
__device__ unsigned            g_mined[BB*PP];     // CE bits (0 for positives)
__device__ unsigned            g_cand[BB*PP];      // compacted candidates
__device__ int                 g_cctr[BB];         // candidate counters
__device__ unsigned long long  g_bpk[BB*TM*OO];    // per-tile best-prior keys
__device__ unsigned long long  g_ovr[BB*OO];       // (pstar<<16)|(bti<<8)|label
__device__ unsigned            g_histp[BB*TC*256]; // per-tile d=3 histograms
__device__ float               g_pll[BB*TC], g_pcep[BB*TC];
__device__ int                 g_pnp[BB*TC];
__device__ float               g_ll[BB], g_lc[BB];
__device__ int                 g_np[BB];

__device__ __forceinline__ float warp_red_f(float v) {
    #pragma unroll
    for (int o = 16; o; o >>= 1) v += __shfl_down_sync(0xffffffffu, v, o);
    return v;
}
__device__ __forceinline__ int warp_red_i(int v) {
    #pragma unroll
    for (int o = 16; o; o >>= 1) v += __shfl_down_sync(0xffffffffu, v, o);
    return v;
}
__device__ __forceinline__ float sl1(float d) {
    float ad = fabsf(d);
    return (ad < 1.0f) ? 0.5f * d * d : ad - 0.5f;
}

// warp-0-collective descending radix digit finder
__device__ __forceinline__ void find_digit(const unsigned* s_hist, int lane, int d,
                                           int* p_kk, unsigned* p_pref, unsigned* p_pmask) {
    unsigned c8[8]; unsigned lsum = 0;
    #pragma unroll
    for (int j = 0; j < 8; j++) { c8[j] = s_hist[lane * 8 + j]; lsum += c8[j]; }
    unsigned sfx = lsum;
    #pragma unroll
    for (int off = 1; off < 32; off <<= 1) {
        unsigned w = __shfl_down_sync(0xffffffffu, sfx, off);
        if (lane + off < 32) sfx += w;
    }
    int kk = *p_kk;
    unsigned bal = __ballot_sync(0xffffffffu, sfx >= (unsigned)kk);
    int L = 31 - __clz(bal);
    if (lane == L) {
        unsigned run = sfx - lsum;
        int dig = 0;
        #pragma unroll
        for (int j = 7; j >= 0; j--) {
            if (run + c8[j] >= (unsigned)kk) { dig = L * 8 + j; break; }
            run += c8[j];
        }
        *p_kk = kk - (int)run;
        *p_pref |= (unsigned)dig << (d * 8);
        *p_pmask |= 0xFFu << (d * 8);
    }
}

// ============ K1: best-prior keys only, grid (TM, BB) x 128 ============
__global__ __launch_bounds__(128, 3) void k_best(
    const float4* __restrict__ priors4, const float* __restrict__ targets)
{
    const int b = blockIdx.y, t = blockIdx.x;
    const int tid = threadIdx.x, lane = tid & 31;

    __shared__ float s_t[OO][5];
    __shared__ unsigned long long s_bpk[OO];

    if (tid < OO * 5) s_t[tid / 5][tid % 5] = targets[b * OO * 5 + tid];
    if (tid < OO) s_bpk[tid] = 0ULL;
    __syncthreads();

    float tx0[OO], ty0[OO], tx1[OO], ty1[OO], ta[OO];
    #pragma unroll
    for (int o = 0; o < OO; o++) {
        tx0[o] = s_t[o][0]; ty0[o] = s_t[o][1];
        tx1[o] = s_t[o][2]; ty1[o] = s_t[o][3];
        ta[o]  = (tx1[o] - tx0[o]) * (ty1[o] - ty0[o]);
    }
    float bIou[OO]; unsigned bP[OO];
    #pragma unroll
    for (int o = 0; o < OO; o++) { bIou[o] = -1.0f; bP[o] = 0u; }

    const int chunk = (PP + TM - 1) / TM;
    const int p0 = t * chunk, p1 = min(p0 + chunk, PP);

    float4 pr = priors4[p0 + tid < PP ? p0 + tid : 0];
    for (int p = p0 + tid; p < p1; p += 128) {
        int pn = p + 128;
        float4 nxt = priors4[pn < p1 ? pn : p];
        float hw = pr.z * 0.5f, hh = pr.w * 0.5f;
        float px0 = pr.x - hw, py0 = pr.y - hh;
        float px1 = pr.x + hw, py1 = pr.y + hh;
        float pa = pr.z * pr.w;
        #pragma unroll
        for (int o = 0; o < OO; o++) {
            float iw = fminf(tx1[o], px1) - fmaxf(tx0[o], px0);
            float ih = fminf(ty1[o], py1) - fmaxf(ty0[o], py0);
            iw = fmaxf(iw, 0.0f); ih = fmaxf(ih, 0.0f);
            float inter = iw * ih;
            float iou = __fdividef(inter, ta[o] + pa - inter);
            if (iou > bIou[o]) { bIou[o] = iou; bP[o] = (unsigned)p; }
        }
        pr = nxt;
    }
    #pragma unroll
    for (int o = 0; o < OO; o++) {
        unsigned long long key =
            ((unsigned long long)__float_as_uint(bIou[o]) << 32) |
            (unsigned long long)(0xFFFFFFFFu - bP[o]);
        #pragma unroll
        for (int off = 16; off; off >>= 1) {
            unsigned long long w = __shfl_down_sync(0xffffffffu, key, off);
            if (w > key) key = w;
        }
        if (lane == 0) atomicMax(&s_bpk[o], key);
    }
    __syncthreads();
    if (tid < OO) g_bpk[(b * TM + t) * OO + tid] = s_bpk[tid];
}

// ============ K2: build override list, grid BB x 32 ============
__global__ void k_override(const float* __restrict__ targets)
{
    const int b = blockIdx.x, lane = threadIdx.x;
    if (lane == 0) g_cctr[b] = 0;
    if (lane < OO) {
        unsigned long long k = 0ULL;
        #pragma unroll
        for (int t = 0; t < TM; t++) {
            unsigned long long v = g_bpk[(b * TM + t) * OO + lane];
            if (v > k) k = v;
        }
        unsigned pstar = 0xFFFFFFFFu - (unsigned)(k & 0xFFFFFFFFULL);
        int lab = (int)targets[b * OO * 5 + lane * 5 + 4];
        g_ovr[b * OO + lane] =
            ((unsigned long long)pstar << 16) | (unsigned)(lab | (lane << 8));
    }
}

// ============ K3: fused match + CE + loc loss + d3 hist, grid (TC, BB) x 128 ============
__global__ __launch_bounds__(128) void k_ce(
    const float4* __restrict__ loc4, const float* __restrict__ conf,
    const float4* __restrict__ priors4, const float* __restrict__ targets)
{
    const int b = blockIdx.y, t = blockIdx.x;
    const int tid = threadIdx.x, lane = tid & 31, wid = tid >> 5;

    __shared__ float4 s_t4[OO];
    __shared__ float  s_area[OO], s_lab[OO];
    __shared__ unsigned long long s_ovr[OO];
    __shared__ float  s_conf[4][32 * CC];
    __shared__ unsigned s_hist[256];
    __shared__ float s_rll[4], s_rcep[4];
    __shared__ int   s_rnp[4];

    if (tid < OO * 5) {
        int o = tid / 5, j = tid % 5;
        float v = targets[b * OO * 5 + tid];
        if (j < 4) ((float*)s_t4)[o * 4 + j] = v;
        else       s_lab[o] = v;
    }
    if (tid < OO) s_ovr[tid] = g_ovr[b * OO + tid];
    for (int i = tid; i < 256; i += 128) s_hist[i] = 0u;
    __syncthreads();
    if (tid < OO) {
        float4 tt = s_t4[tid];
        s_area[tid] = (tt.z - tt.x) * (tt.w - tt.y);
    }
    __syncthreads();

    const int wt0 = t * TPC, wt1 = min(wt0 + TPC, NTILES);
    float ll = 0.0f, cep = 0.0f; int np = 0;

    for (int wt = wt0 + wid; wt < wt1; wt += 4) {
        int p32 = wt * 32;
        const float* cb = conf + ((size_t)b * PP + p32) * CC;
        float* sc = s_conf[wid];
        if (p32 + 32 <= PP) {
            #pragma unroll
            for (int i = 0; i < CC; i++) sc[i * 32 + lane] = cb[i * 32 + lane];
        } else {
            int lim = (PP - p32) * CC;
            #pragma unroll
            for (int i = 0; i < CC; i++) {
                int j = i * 32 + lane;
                sc[j] = cb[j < lim ? j : 0];
            }
        }
        __syncwarp();
        int n = min(32, PP - p32);
        bool actv = lane < n;
        int p = p32 + (actv ? lane : 0);

        // inline match (identical comparator to the two-pass version)
        int ct = 0, bti = 0;
        float4 pq;
        if (actv) {
            pq = priors4[p];
            float hw = pq.z * 0.5f, hh = pq.w * 0.5f;
            float px0 = pq.x - hw, py0 = pq.y - hh;
            float px1 = pq.x + hw, py1 = pq.y + hh;
            float pa = pq.z * pq.w;
            float bto = -1.0f;
            #pragma unroll
            for (int o = 0; o < OO; o++) {
                float4 tt = s_t4[o];               // LDS.128 broadcast
                float ar = s_area[o];
                float iw = fminf(tt.z, px1) - fmaxf(tt.x, px0);
                float ih = fminf(tt.w, py1) - fmaxf(tt.y, py0);
                iw = fmaxf(iw, 0.0f); ih = fmaxf(ih, 0.0f);
                float inter = iw * ih;
                float iou = __fdividef(inter, ar + pa - inter);
                if (iou > bto) { bto = iou; bti = o; }
            }
            ct = (bto >= THRESH) ? (int)s_lab[bti] : 0;
        }
        // override check: does any best-prior land in this tile?
        bool h = false;
        if (lane < OO) {
            unsigned ps = (unsigned)(s_ovr[lane] >> 16);
            h = (ps >> 5) == (unsigned)wt;
        }
        unsigned hb = __ballot_sync(0xffffffffu, h);
        if (hb && actv) {
            #pragma unroll
            for (int o = 0; o < OO; o++) {          // ascending: last-wins
                unsigned long long e = s_ovr[o];
                if ((unsigned)(e >> 16) == (unsigned)p) {
                    ct = (int)(e & 0xFFu); bti = (int)((e >> 8) & 0xFFu);
                }
            }
        }

        unsigned u = 0u;
        if (actv) {
            const float* row = sc + lane * CC;     // stride 21: conflict-free
            float s0 = 0.0f, s1 = 0.0f;
            #pragma unroll
            for (int c = 0; c < CC - 1; c += 2) {
                s0 += __expf(row[c]);
                s1 += __expf(row[c + 1]);
            }
            s0 += __expf(row[CC - 1]);
            float lse = __logf(s0 + s1);
            float ce = lse - row[ct];
            bool pos = ct > 0;
            u = pos ? 0u : __float_as_uint(fmaxf(ce, 0.0f));
            g_mined[(size_t)b * PP + p] = u;
            if (pos) {
                cep += ce; np++;
                float4 ld = loc4[(size_t)b * PP + p];
                float4 tt = s_t4[bti];
                float gx = __fdividef((tt.x + tt.z) * 0.5f - pq.x, VAR0 * pq.z);
                float gy = __fdividef((tt.y + tt.w) * 0.5f - pq.y, VAR0 * pq.w);
                float gw = __logf(__fdividef(tt.z - tt.x, pq.z)) * (1.0f / VAR1);
                float gh = __logf(__fdividef(tt.w - tt.y, pq.w)) * (1.0f / VAR1);
                ll += sl1(ld.x - gx) + sl1(ld.y - gy) +
                      sl1(ld.z - gw) + sl1(ld.w - gh);
            }
        }
        unsigned ab = __ballot_sync(0xffffffffu, actv);
        if (actv) {
            unsigned dig = u >> 24;
            unsigned peers = __match_any_sync(ab, dig);
            if ((peers & ((1u << lane) - 1)) == 0)
                atomicAdd(&s_hist[dig], (unsigned)__popc(peers));
        }
        __syncwarp();
    }

    ll = warp_red_f(ll); cep = warp_red_f(cep); np = warp_red_i(np);
    if (lane == 0) { s_rll[wid] = ll; s_rcep[wid] = cep; s_rnp[wid] = np; }
    __syncthreads();
    if (tid == 0) {
        float a = 0.0f, c = 0.0f; int nn = 0;
        #pragma unroll
        for (int w = 0; w < 4; w++) { a += s_rll[w]; c += s_rcep[w]; nn += s_rnp[w]; }
        g_pll[b * TC + t] = a; g_pcep[b * TC + t] = c; g_pnp[b * TC + t] = nn;
    }
    for (int i = tid; i < 256; i += 128) g_histp[(b * TC + t) * 256 + i] = s_hist[i];
}

// ============ K4: select via compaction, grid BB x 512 ============
__global__ __launch_bounds__(512, 1) void k_select()
{
    const int b = blockIdx.x;
    const int tid = threadIdx.x, lane = tid & 31, wid = tid >> 5;
    __shared__ unsigned s_hist[256];
    __shared__ float s_r[16];
    __shared__ float s_sgt;
    __shared__ int sh_kk, s_nc;
    __shared__ unsigned sh_pref, sh_pmask;
    __shared__ float s_llT, s_cepT, s_negT;
    __shared__ int s_npT;

    if (wid == 0) {
        float a = (lane < TC) ? g_pll[b * TC + lane] : 0.0f;
        float c = (lane < TC) ? g_pcep[b * TC + lane] : 0.0f;
        int   n = (lane < TC) ? g_pnp[b * TC + lane] : 0;
        a = warp_red_f(a); c = warp_red_f(c); n = warp_red_i(n);
        if (lane == 0) {
            s_llT = a; s_cepT = c; s_npT = n;
            int k = NEGPOS * n; if (k > PP - 1) k = PP - 1;
            sh_kk = k; sh_pref = 0u; sh_pmask = 0u;
            s_negT = 0.0f; s_sgt = 0.0f;
        }
    }
    if (tid < 256) {
        unsigned hsum = 0;
        #pragma unroll
        for (int t = 0; t < TC; t++) hsum += g_histp[(b * TC + t) * 256 + tid];
        s_hist[tid] = hsum;
    }
    __syncthreads();

    if (sh_kk > 0) {
        if (wid == 0) find_digit(s_hist, lane, 3, &sh_kk, &sh_pref, &sh_pmask);
        __syncthreads();
        const unsigned dig3 = sh_pref >> 24;
        unsigned* cand = g_cand + (size_t)b * PP;

        // ONE full scan: deterministic sum of top>dig3, compact top==dig3
        float sgt = 0.0f;
        for (int base = 0; base < PP; base += 512 * 8) {
            #pragma unroll
            for (int j = 0; j < 8; j++) {
                int p = base + j * 512 + tid;
                unsigned x = (p < PP) ? g_mined[(size_t)b * PP + p] : 0u;
                unsigned top = x >> 24;
                bool eq = (p < PP) && (top == dig3);
                if ((p < PP) && (top > dig3)) sgt += __uint_as_float(x);
                unsigned bal = __ballot_sync(0xffffffffu, eq);
                if (eq) {
                    int leader = __ffs(bal) - 1;
                    int basei = 0;
                    if (lane == leader) basei = atomicAdd(&g_cctr[b], __popc(bal));
                    basei = __shfl_sync(bal, basei, leader);
                    cand[basei + __popc(bal & ((1u << lane) - 1))] = x;
                }
            }
        }
        sgt = warp_red_f(sgt);
        if (lane == 0) s_r[wid] = sgt;
        __syncthreads();
        if (tid == 0) {
            float tot = 0.0f;
            #pragma unroll
            for (int w = 0; w < 16; w++) tot += s_r[w];
            s_sgt = tot;
            s_nc = g_cctr[b];
        }
        __syncthreads();
        const int nc = s_nc;

        // remaining radix levels on candidates only
        for (int d = 2; d >= 0; d--) {
            for (int i = tid; i < 256; i += 512) s_hist[i] = 0u;
            __syncthreads();
            unsigned pref = sh_pref, pmask = sh_pmask;
            for (int base = 0; base < nc; base += 512) {
                int p = base + tid;
                unsigned x = (p < nc) ? cand[p] : 0u;
                bool v = (p < nc) && ((x & pmask) == pref);
                unsigned ab = __ballot_sync(0xffffffffu, v);
                if (v) {
                    unsigned dig = (x >> (d * 8)) & 0xFFu;
                    unsigned peers = __match_any_sync(ab, dig);
                    if ((peers & ((1u << lane) - 1)) == 0)
                        atomicAdd(&s_hist[dig], (unsigned)__popc(peers));
                }
            }
            __syncthreads();
            if (wid == 0) find_digit(s_hist, lane, d, &sh_kk, &sh_pref, &sh_pmask);
            __syncthreads();
        }

        unsigned vb = sh_pref;
        float s = 0.0f;
        for (int p = tid; p < nc; p += 512) {
            unsigned x = cand[p];
            if (x > vb) s += __uint_as_float(x);
        }
        s = warp_red_f(s);
        if (lane == 0) s_r[wid] = s;
        __syncthreads();
        if (tid == 0) {
            float tot = 0.0f;
            #pragma unroll
            for (int w = 0; w < 16; w++) tot += s_r[w];
            s_negT = s_sgt + tot + __uint_as_float(vb) * (float)sh_kk;
        }
        __syncthreads();
    }

    if (tid == 0) {
        g_ll[b] = s_llT;
        g_lc[b] = s_cepT + s_negT;
        g_np[b] = s_npT;
    }
}

// ============ K5: finalize ============
__global__ void mb_fin(float* __restrict__ out) {
    const int t = threadIdx.x;   // 128 threads
    const int lane = t & 31, wid = t >> 5;
    __shared__ float s_a[4], s_b[4];
    __shared__ int s_n[4];
    float ll = g_ll[t], lc = g_lc[t];
    int np = g_np[t];
    ll = warp_red_f(ll); lc = warp_red_f(lc); np = warp_red_i(np);
    if (lane == 0) { s_a[wid] = ll; s_b[wid] = lc; s_n[wid] = np; }
    __syncthreads();
    if (t == 0) {
        float llT = 0.0f, lcT = 0.0f; int npT = 0;
        for (int w = 0; w < 4; w++) { llT += s_a[w]; lcT += s_b[w]; npT += s_n[w]; }
        float N = (npT > 0) ? (float)npT : (float)BB;
        out[0] = llT / N;
        out[1] = lcT / N;
    }
}

extern "C" void kernel_launch(void* const* d_in, const int* in_sizes, int n_in,
                              void* d_out, int out_size) {
    const float4* loc4    = (const float4*)d_in[0];   // [B,P,4]
    const float*  conf    = (const float*)d_in[1];    // [B,P,21]
    const float4* priors4 = (const float4*)d_in[2];   // [P,4]
    const float*  targets = (const float*)d_in[3];    // [B,16,5]
    float* out = (float*)d_out;

    k_best<<<dim3(TM, BB), 128>>>(priors4, targets);
    k_override<<<BB, 32>>>(targets);
    k_ce<<<dim3(TC, BB), 128>>>(loc4, conf, priors4, targets);
    k_select<<<BB, 512>>>();
    mb_fin<<<1, 128>>>(out);
}

// round 13
// speedup vs baseline: 1.2157x; 1.2157x over previous
#include <cuda_runtime.h>

#define BB 128
#define PP 34125
#define OO 16
#define CC 21
#define NEGPOS 3
#define VAR0 0.1f
#define VAR1 0.2f
#define THRESH 0.35f
#define TM 16                // best-prior tiles per batch
#define TC 16                // CE tiles per batch
#define NTILES ((PP + 31) / 32)          // 1067
#define TPC ((NTILES + TC - 1) / TC)     // 67 warp-tiles per CE CTA

// scratch (device globals; every word read is written earlier in the same call)
__device__ unsigned            g_mined[BB*PP];     // CE bits (0 for positives)
__device__ unsigned            g_cand[BB*PP];      // compacted candidates
__device__ unsigned long long  g_bpk[BB*TM*OO];    // per-tile best-prior keys
__device__ unsigned long long  g_ovr[BB*OO];       // (pstar<<16)|(bti<<8)|label
__device__ unsigned            g_histp[BB*TC*256]; // per-tile d=3 histograms
__device__ float               g_pll[BB*TC], g_pcep[BB*TC];
__device__ int                 g_pnp[BB*TC];
__device__ float               g_ll[BB], g_lc[BB];
__device__ int                 g_np[BB];

__device__ __forceinline__ float warp_red_f(float v) {
    #pragma unroll
    for (int o = 16; o; o >>= 1) v += __shfl_down_sync(0xffffffffu, v, o);
    return v;
}
__device__ __forceinline__ int warp_red_i(int v) {
    #pragma unroll
    for (int o = 16; o; o >>= 1) v += __shfl_down_sync(0xffffffffu, v, o);
    return v;
}
__device__ __forceinline__ float sl1(float d) {
    float ad = fabsf(d);
    return (ad < 1.0f) ? 0.5f * d * d : ad - 0.5f;
}

// warp-0-collective descending radix digit finder
__device__ __forceinline__ void find_digit(const unsigned* s_hist, int lane, int d,
                                           int* p_kk, unsigned* p_pref, unsigned* p_pmask) {
    unsigned c8[8]; unsigned lsum = 0;
    #pragma unroll
    for (int j = 0; j < 8; j++) { c8[j] = s_hist[lane * 8 + j]; lsum += c8[j]; }
    unsigned sfx = lsum;
    #pragma unroll
    for (int off = 1; off < 32; off <<= 1) {
        unsigned w = __shfl_down_sync(0xffffffffu, sfx, off);
        if (lane + off < 32) sfx += w;
    }
    int kk = *p_kk;
    unsigned bal = __ballot_sync(0xffffffffu, sfx >= (unsigned)kk);
    int L = 31 - __clz(bal);
    if (lane == L) {
        unsigned run = sfx - lsum;
        int dig = 0;
        #pragma unroll
        for (int j = 7; j >= 0; j--) {
            if (run + c8[j] >= (unsigned)kk) { dig = L * 8 + j; break; }
            run += c8[j];
        }
        *p_kk = kk - (int)run;
        *p_pref |= (unsigned)dig << (d * 8);
        *p_pmask |= 0xFFu << (d * 8);
    }
}

// ============ K1: best-prior keys only, grid (TM, BB) x 128 ============
__global__ __launch_bounds__(128, 3) void k_best(
    const float4* __restrict__ priors4, const float* __restrict__ targets)
{
    const int b = blockIdx.y, t = blockIdx.x;
    const int tid = threadIdx.x, lane = tid & 31;

    __shared__ float s_t[OO][5];
    __shared__ unsigned long long s_bpk[OO];

    if (tid < OO * 5) s_t[tid / 5][tid % 5] = targets[b * OO * 5 + tid];
    if (tid < OO) s_bpk[tid] = 0ULL;
    __syncthreads();

    float tx0[OO], ty0[OO], tx1[OO], ty1[OO], ta[OO];
    #pragma unroll
    for (int o = 0; o < OO; o++) {
        tx0[o] = s_t[o][0]; ty0[o] = s_t[o][1];
        tx1[o] = s_t[o][2]; ty1[o] = s_t[o][3];
        ta[o]  = (tx1[o] - tx0[o]) * (ty1[o] - ty0[o]);
    }
    float bIou[OO]; unsigned bP[OO];
    #pragma unroll
    for (int o = 0; o < OO; o++) { bIou[o] = -1.0f; bP[o] = 0u; }

    const int chunk = (PP + TM - 1) / TM;
    const int p0 = t * chunk, p1 = min(p0 + chunk, PP);

    float4 pr = priors4[p0 + tid < PP ? p0 + tid : 0];
    for (int p = p0 + tid; p < p1; p += 128) {
        int pn = p + 128;
        float4 nxt = priors4[pn < p1 ? pn : p];
        float hw = pr.z * 0.5f, hh = pr.w * 0.5f;
        float px0 = pr.x - hw, py0 = pr.y - hh;
        float px1 = pr.x + hw, py1 = pr.y + hh;
        float pa = pr.z * pr.w;
        #pragma unroll
        for (int o = 0; o < OO; o++) {
            float iw = fminf(tx1[o], px1) - fmaxf(tx0[o], px0);
            float ih = fminf(ty1[o], py1) - fmaxf(ty0[o], py0);
            iw = fmaxf(iw, 0.0f); ih = fmaxf(ih, 0.0f);
            float inter = iw * ih;
            float iou = __fdividef(inter, ta[o] + pa - inter);
            if (iou > bIou[o]) { bIou[o] = iou; bP[o] = (unsigned)p; }
        }
        pr = nxt;
    }
    #pragma unroll
    for (int o = 0; o < OO; o++) {
        unsigned long long key =
            ((unsigned long long)__float_as_uint(bIou[o]) << 32) |
            (unsigned long long)(0xFFFFFFFFu - bP[o]);
        #pragma unroll
        for (int off = 16; off; off >>= 1) {
            unsigned long long w = __shfl_down_sync(0xffffffffu, key, off);
            if (w > key) key = w;
        }
        if (lane == 0) atomicMax(&s_bpk[o], key);
    }
    __syncthreads();
    if (tid < OO) g_bpk[(b * TM + t) * OO + tid] = s_bpk[tid];
}

// ============ K2: build override list, grid BB x 32 ============
__global__ void k_override(const float* __restrict__ targets)
{
    const int b = blockIdx.x, lane = threadIdx.x;
    if (lane < OO) {
        unsigned long long k = 0ULL;
        #pragma unroll
        for (int t = 0; t < TM; t++) {
            unsigned long long v = g_bpk[(b * TM + t) * OO + lane];
            if (v > k) k = v;
        }
        unsigned pstar = 0xFFFFFFFFu - (unsigned)(k & 0xFFFFFFFFULL);
        int lab = (int)targets[b * OO * 5 + lane * 5 + 4];
        g_ovr[b * OO + lane] =
            ((unsigned long long)pstar << 16) | (unsigned)(lab | (lane << 8));
    }
}

// ============ K3: fused match + CE + loc loss + d3 hist, grid (TC, BB) x 128 ============
__global__ __launch_bounds__(128) void k_ce(
    const float4* __restrict__ loc4, const float* __restrict__ conf,
    const float4* __restrict__ priors4, const float* __restrict__ targets)
{
    const int b = blockIdx.y, t = blockIdx.x;
    const int tid = threadIdx.x, lane = tid & 31, wid = tid >> 5;

    __shared__ float4 s_t4[OO];
    __shared__ float  s_area[OO], s_lab[OO];
    __shared__ unsigned long long s_ovr[OO];
    __shared__ float  s_conf[4][32 * CC];
    __shared__ unsigned s_hist[256];
    __shared__ float s_rll[4], s_rcep[4];
    __shared__ int   s_rnp[4];

    if (tid < OO * 5) {
        int o = tid / 5, j = tid % 5;
        float v = targets[b * OO * 5 + tid];
        if (j < 4) ((float*)s_t4)[o * 4 + j] = v;
        else       s_lab[o] = v;
    }
    if (tid < OO) s_ovr[tid] = g_ovr[b * OO + tid];
    for (int i = tid; i < 256; i += 128) s_hist[i] = 0u;
    __syncthreads();
    if (tid < OO) {
        float4 tt = s_t4[tid];
        s_area[tid] = (tt.z - tt.x) * (tt.w - tt.y);
    }
    __syncthreads();

    const int wt0 = t * TPC, wt1 = min(wt0 + TPC, NTILES);
    float ll = 0.0f, cep = 0.0f; int np = 0;

    for (int wt = wt0 + wid; wt < wt1; wt += 4) {
        int p32 = wt * 32;
        const float* cb = conf + ((size_t)b * PP + p32) * CC;
        float* sc = s_conf[wid];
        if (p32 + 32 <= PP) {
            #pragma unroll
            for (int i = 0; i < CC; i++) sc[i * 32 + lane] = cb[i * 32 + lane];
        } else {
            int lim = (PP - p32) * CC;
            #pragma unroll
            for (int i = 0; i < CC; i++) {
                int j = i * 32 + lane;
                sc[j] = cb[j < lim ? j : 0];
            }
        }
        __syncwarp();
        int n = min(32, PP - p32);
        bool actv = lane < n;
        int p = p32 + (actv ? lane : 0);

        // inline match (identical comparator to the two-pass version)
        int ct = 0, bti = 0;
        float4 pq;
        if (actv) {
            pq = priors4[p];
            float hw = pq.z * 0.5f, hh = pq.w * 0.5f;
            float px0 = pq.x - hw, py0 = pq.y - hh;
            float px1 = pq.x + hw, py1 = pq.y + hh;
            float pa = pq.z * pq.w;
            float bto = -1.0f;
            #pragma unroll
            for (int o = 0; o < OO; o++) {
                float4 tt = s_t4[o];               // LDS.128 broadcast
                float ar = s_area[o];
                float iw = fminf(tt.z, px1) - fmaxf(tt.x, px0);
                float ih = fminf(tt.w, py1) - fmaxf(tt.y, py0);
                iw = fmaxf(iw, 0.0f); ih = fmaxf(ih, 0.0f);
                float inter = iw * ih;
                float iou = __fdividef(inter, ar + pa - inter);
                if (iou > bto) { bto = iou; bti = o; }
            }
            ct = (bto >= THRESH) ? (int)s_lab[bti] : 0;
        }
        // override check: does any best-prior land in this tile?
        bool h = false;
        if (lane < OO) {
            unsigned ps = (unsigned)(s_ovr[lane] >> 16);
            h = (ps >> 5) == (unsigned)wt;
        }
        unsigned hb = __ballot_sync(0xffffffffu, h);
        if (hb && actv) {
            #pragma unroll
            for (int o = 0; o < OO; o++) {          // ascending: last-wins
                unsigned long long e = s_ovr[o];
                if ((unsigned)(e >> 16) == (unsigned)p) {
                    ct = (int)(e & 0xFFu); bti = (int)((e >> 8) & 0xFFu);
                }
            }
        }

        unsigned u = 0u;
        if (actv) {
            const float* row = sc + lane * CC;     // stride 21: conflict-free
            float s0 = 0.0f, s1 = 0.0f;
            #pragma unroll
            for (int c = 0; c < CC - 1; c += 2) {
                s0 += __expf(row[c]);
                s1 += __expf(row[c + 1]);
            }
            s0 += __expf(row[CC - 1]);
            float lse = __logf(s0 + s1);
            float ce = lse - row[ct];
            bool pos = ct > 0;
            u = pos ? 0u : __float_as_uint(fmaxf(ce, 0.0f));
            g_mined[(size_t)b * PP + p] = u;
            if (pos) {
                cep += ce; np++;
                float4 ld = loc4[(size_t)b * PP + p];
                float4 tt = s_t4[bti];
                float gx = __fdividef((tt.x + tt.z) * 0.5f - pq.x, VAR0 * pq.z);
                float gy = __fdividef((tt.y + tt.w) * 0.5f - pq.y, VAR0 * pq.w);
                float gw = __logf(__fdividef(tt.z - tt.x, pq.z)) * (1.0f / VAR1);
                float gh = __logf(__fdividef(tt.w - tt.y, pq.w)) * (1.0f / VAR1);
                ll += sl1(ld.x - gx) + sl1(ld.y - gy) +
                      sl1(ld.z - gw) + sl1(ld.w - gh);
            }
        }
        unsigned ab = __ballot_sync(0xffffffffu, actv);
        if (actv) {
            unsigned dig = u >> 24;
            unsigned peers = __match_any_sync(ab, dig);
            if ((peers & ((1u << lane) - 1)) == 0)
                atomicAdd(&s_hist[dig], (unsigned)__popc(peers));
        }
        __syncwarp();
    }

    ll = warp_red_f(ll); cep = warp_red_f(cep); np = warp_red_i(np);
    if (lane == 0) { s_rll[wid] = ll; s_rcep[wid] = cep; s_rnp[wid] = np; }
    __syncthreads();
    if (tid == 0) {
        float a = 0.0f, c = 0.0f; int nn = 0;
        #pragma unroll
        for (int w = 0; w < 4; w++) { a += s_rll[w]; c += s_rcep[w]; nn += s_rnp[w]; }
        g_pll[b * TC + t] = a; g_pcep[b * TC + t] = c; g_pnp[b * TC + t] = nn;
    }
    for (int i = tid; i < 256; i += 128) g_histp[(b * TC + t) * 256 + i] = s_hist[i];
}

// ============ K4: select via compaction (batched loads + SMEM counter), grid BB x 512 ============
__global__ __launch_bounds__(512, 1) void k_select()
{
    const int b = blockIdx.x;
    const int tid = threadIdx.x, lane = tid & 31, wid = tid >> 5;
    __shared__ unsigned s_hist[256];
    __shared__ float s_r[16];
    __shared__ float s_sgt;
    __shared__ int sh_kk;
    __shared__ int s_cctr;                  // CTA-local candidate counter
    __shared__ unsigned sh_pref, sh_pmask;
    __shared__ float s_llT, s_cepT, s_negT;
    __shared__ int s_npT;

    if (wid == 0) {
        float a = (lane < TC) ? g_pll[b * TC + lane] : 0.0f;
        float c = (lane < TC) ? g_pcep[b * TC + lane] : 0.0f;
        int   n = (lane < TC) ? g_pnp[b * TC + lane] : 0;
        a = warp_red_f(a); c = warp_red_f(c); n = warp_red_i(n);
        if (lane == 0) {
            s_llT = a; s_cepT = c; s_npT = n;
            int k = NEGPOS * n; if (k > PP - 1) k = PP - 1;
            sh_kk = k; sh_pref = 0u; sh_pmask = 0u;
            s_negT = 0.0f; s_sgt = 0.0f; s_cctr = 0;
        }
    }
    if (tid < 256) {
        unsigned hsum = 0;
        #pragma unroll
        for (int t = 0; t < TC; t++) hsum += g_histp[(b * TC + t) * 256 + tid];
        s_hist[tid] = hsum;
    }
    __syncthreads();

    if (sh_kk > 0) {
        if (wid == 0) find_digit(s_hist, lane, 3, &sh_kk, &sh_pref, &sh_pmask);
        __syncthreads();
        const unsigned dig3 = sh_pref >> 24;
        unsigned* cand = g_cand + (size_t)b * PP;
        const unsigned* mined = g_mined + (size_t)b * PP;

        // ONE full scan, MLP-8: sum top>dig3, compact top==dig3 (SMEM counter)
        float sgt = 0.0f;
        for (int base = 0; base < PP; base += 512 * 8) {
            unsigned xx[8];
            #pragma unroll
            for (int j = 0; j < 8; j++) {               // batched loads first
                int p = base + j * 512 + tid;
                xx[j] = (p < PP) ? mined[p] : 0u;
            }
            #pragma unroll
            for (int j = 0; j < 8; j++) {
                int p = base + j * 512 + tid;
                unsigned x = xx[j];
                unsigned top = x >> 24;
                bool valid = p < PP;
                if (valid && top > dig3) sgt += __uint_as_float(x);
                bool eq = valid && (top == dig3);
                unsigned bal = __ballot_sync(0xffffffffu, eq);
                if (bal) {
                    int leader = __ffs(bal) - 1;
                    int basei = 0;
                    if (lane == leader) basei = atomicAdd(&s_cctr, __popc(bal));
                    basei = __shfl_sync(0xffffffffu, basei, leader);
                    if (eq) cand[basei + __popc(bal & ((1u << lane) - 1))] = x;
                }
            }
        }
        sgt = warp_red_f(sgt);
        if (lane == 0) s_r[wid] = sgt;
        __syncthreads();
        if (tid == 0) {
            float tot = 0.0f;
            #pragma unroll
            for (int w = 0; w < 16; w++) tot += s_r[w];
            s_sgt = tot;
        }
        __syncthreads();
        const int nc = s_cctr;

        // remaining radix levels on candidates only
        for (int d = 2; d >= 0; d--) {
            for (int i = tid; i < 256; i += 512) s_hist[i] = 0u;
            __syncthreads();
            unsigned pref = sh_pref, pmask = sh_pmask;
            for (int base = 0; base < nc; base += 512 * 4) {
                unsigned xx[4];
                #pragma unroll
                for (int j = 0; j < 4; j++) {
                    int p = base + j * 512 + tid;
                    xx[j] = (p < nc) ? cand[p] : 0u;
                }
                #pragma unroll
                for (int j = 0; j < 4; j++) {
                    int p = base + j * 512 + tid;
                    bool v = (p < nc) && ((xx[j] & pmask) == pref);
                    unsigned ab = __ballot_sync(0xffffffffu, v);
                    if (v) {
                        unsigned dig = (xx[j] >> (d * 8)) & 0xFFu;
                        unsigned peers = __match_any_sync(ab, dig);
                        if ((peers & ((1u << lane) - 1)) == 0)
                            atomicAdd(&s_hist[dig], (unsigned)__popc(peers));
                    }
                }
            }
            __syncthreads();
            if (wid == 0) find_digit(s_hist, lane, d, &sh_kk, &sh_pref, &sh_pmask);
            __syncthreads();
        }

        unsigned vb = sh_pref;
        float s = 0.0f;
        for (int p = tid; p < nc; p += 512) {
            unsigned x = cand[p];
            if (x > vb) s += __uint_as_float(x);
        }
        s = warp_red_f(s);
        if (lane == 0) s_r[wid] = s;
        __syncthreads();
        if (tid == 0) {
            float tot = 0.0f;
            #pragma unroll
            for (int w = 0; w < 16; w++) tot += s_r[w];
            s_negT = s_sgt + tot + __uint_as_float(vb) * (float)sh_kk;
        }
        __syncthreads();
    }

    if (tid == 0) {
        g_ll[b] = s_llT;
        g_lc[b] = s_cepT + s_negT;
        g_np[b] = s_npT;
    }
}

// ============ K5: finalize ============
__global__ void mb_fin(float* __restrict__ out) {
    const int t = threadIdx.x;   // 128 threads
    const int lane = t & 31, wid = t >> 5;
    __shared__ float s_a[4], s_b[4];
    __shared__ int s_n[4];
    float ll = g_ll[t], lc = g_lc[t];
    int np = g_np[t];
    ll = warp_red_f(ll); lc = warp_red_f(lc); np = warp_red_i(np);
    if (lane == 0) { s_a[wid] = ll; s_b[wid] = lc; s_n[wid] = np; }
    __syncthreads();
    if (t == 0) {
        float llT = 0.0f, lcT = 0.0f; int npT = 0;
        for (int w = 0; w < 4; w++) { llT += s_a[w]; lcT += s_b[w]; npT += s_n[w]; }
        float N = (npT > 0) ? (float)npT : (float)BB;
        out[0] = llT / N;
        out[1] = lcT / N;
    }
}

extern "C" void kernel_launch(void* const* d_in, const int* in_sizes, int n_in,
                              void* d_out, int out_size) {
    const float4* loc4    = (const float4*)d_in[0];   // [B,P,4]
    const float*  conf    = (const float*)d_in[1];    // [B,P,21]
    const float4* priors4 = (const float4*)d_in[2];   // [P,4]
    const float*  targets = (const float*)d_in[3];    // [B,16,5]
    float* out = (float*)d_out;

    k_best<<<dim3(TM, BB), 128>>>(priors4, targets);
    k_override<<<BB, 32>>>(targets);
    k_ce<<<dim3(TC, BB), 128>>>(loc4, conf, priors4, targets);
    k_select<<<BB, 512>>>();
    mb_fin<<<1, 128>>>(out);
}

// round 14
// speedup vs baseline: 1.3320x; 1.0956x over previous
#include <cuda_runtime.h>

#define BB 128
#define PP 34125
#define OO 16
#define CC 21
#define NEGPOS 3
#define VAR0 0.1f
#define VAR1 0.2f
#define THRESH 0.35f
#define TM 16                // best-prior tiles per batch
#define TC 16                // CE tiles per batch
#define NTILES ((PP + 31) / 32)          // 1067
#define TPC ((NTILES + TC - 1) / TC)     // 67 warp-tiles per CE CTA

// scratch (device globals; every word read is written earlier in the same call)
__device__ unsigned            g_mined[BB*PP];     // CE bits (0 for positives)
__device__ unsigned            g_cand[BB*PP];      // compacted candidates
__device__ unsigned long long  g_bpk[BB*TM*OO];    // per-tile best-prior keys
__device__ unsigned long long  g_ovr[BB*OO];       // (pstar<<16)|(bti<<8)|label
__device__ float               g_pll[BB*TC], g_pcep[BB*TC];
__device__ int                 g_pnp[BB*TC];
__device__ float               g_ll[BB], g_lc[BB];
__device__ int                 g_np[BB];

__device__ __forceinline__ float warp_red_f(float v) {
    #pragma unroll
    for (int o = 16; o; o >>= 1) v += __shfl_down_sync(0xffffffffu, v, o);
    return v;
}
__device__ __forceinline__ int warp_red_i(int v) {
    #pragma unroll
    for (int o = 16; o; o >>= 1) v += __shfl_down_sync(0xffffffffu, v, o);
    return v;
}
__device__ __forceinline__ float sl1(float d) {
    float ad = fabsf(d);
    return (ad < 1.0f) ? 0.5f * d * d : ad - 0.5f;
}

// warp-0-collective: find crossing digit in a 256-bin histogram (descending).
// Generic shift; ORs dig<<shift into pref and 0xFF<<shift into pmask.
__device__ __forceinline__ void find_digit256(const unsigned* s_hist, int lane, int shift,
                                              int* p_kk, unsigned* p_pref, unsigned* p_pmask) {
    unsigned c8[8]; unsigned lsum = 0;
    #pragma unroll
    for (int j = 0; j < 8; j++) { c8[j] = s_hist[lane * 8 + j]; lsum += c8[j]; }
    unsigned sfx = lsum;
    #pragma unroll
    for (int off = 1; off < 32; off <<= 1) {
        unsigned w = __shfl_down_sync(0xffffffffu, sfx, off);
        if (lane + off < 32) sfx += w;
    }
    int kk = *p_kk;
    unsigned bal = __ballot_sync(0xffffffffu, sfx >= (unsigned)kk);
    int L = 31 - __clz(bal);
    if (lane == L) {
        unsigned run = sfx - lsum;
        int dig = 0;
        #pragma unroll
        for (int j = 7; j >= 0; j--) {
            if (run + c8[j] >= (unsigned)kk) { dig = L * 8 + j; break; }
            run += c8[j];
        }
        *p_kk = kk - (int)run;
        *p_pref |= (unsigned)dig << shift;
        *p_pmask |= 0xFFu << shift;
    }
}

// ============ K1: best-prior keys only, grid (TM, BB) x 128 ============
__global__ __launch_bounds__(128, 3) void k_best(
    const float4* __restrict__ priors4, const float* __restrict__ targets)
{
    const int b = blockIdx.y, t = blockIdx.x;
    const int tid = threadIdx.x, lane = tid & 31;

    __shared__ float s_t[OO][5];
    __shared__ unsigned long long s_bpk[OO];

    if (tid < OO * 5) s_t[tid / 5][tid % 5] = targets[b * OO * 5 + tid];
    if (tid < OO) s_bpk[tid] = 0ULL;
    __syncthreads();

    float tx0[OO], ty0[OO], tx1[OO], ty1[OO], ta[OO];
    #pragma unroll
    for (int o = 0; o < OO; o++) {
        tx0[o] = s_t[o][0]; ty0[o] = s_t[o][1];
        tx1[o] = s_t[o][2]; ty1[o] = s_t[o][3];
        ta[o]  = (tx1[o] - tx0[o]) * (ty1[o] - ty0[o]);
    }
    float bIou[OO]; unsigned bP[OO];
    #pragma unroll
    for (int o = 0; o < OO; o++) { bIou[o] = -1.0f; bP[o] = 0u; }

    const int chunk = (PP + TM - 1) / TM;
    const int p0 = t * chunk, p1 = min(p0 + chunk, PP);

    float4 pr = priors4[p0 + tid < PP ? p0 + tid : 0];
    for (int p = p0 + tid; p < p1; p += 128) {
        int pn = p + 128;
        float4 nxt = priors4[pn < p1 ? pn : p];
        float hw = pr.z * 0.5f, hh = pr.w * 0.5f;
        float px0 = pr.x - hw, py0 = pr.y - hh;
        float px1 = pr.x + hw, py1 = pr.y + hh;
        float pa = pr.z * pr.w;
        #pragma unroll
        for (int o = 0; o < OO; o++) {
            float iw = fminf(tx1[o], px1) - fmaxf(tx0[o], px0);
            float ih = fminf(ty1[o], py1) - fmaxf(ty0[o], py0);
            iw = fmaxf(iw, 0.0f); ih = fmaxf(ih, 0.0f);
            float inter = iw * ih;
            float iou = __fdividef(inter, ta[o] + pa - inter);
            if (iou > bIou[o]) { bIou[o] = iou; bP[o] = (unsigned)p; }
        }
        pr = nxt;
    }
    #pragma unroll
    for (int o = 0; o < OO; o++) {
        unsigned long long key =
            ((unsigned long long)__float_as_uint(bIou[o]) << 32) |
            (unsigned long long)(0xFFFFFFFFu - bP[o]);
        #pragma unroll
        for (int off = 16; off; off >>= 1) {
            unsigned long long w = __shfl_down_sync(0xffffffffu, key, off);
            if (w > key) key = w;
        }
        if (lane == 0) atomicMax(&s_bpk[o], key);
    }
    __syncthreads();
    if (tid < OO) g_bpk[(b * TM + t) * OO + tid] = s_bpk[tid];
}

// ============ K2: build override list, grid BB x 32 ============
__global__ void k_override(const float* __restrict__ targets)
{
    const int b = blockIdx.x, lane = threadIdx.x;
    if (lane < OO) {
        unsigned long long k = 0ULL;
        #pragma unroll
        for (int t = 0; t < TM; t++) {
            unsigned long long v = g_bpk[(b * TM + t) * OO + lane];
            if (v > k) k = v;
        }
        unsigned pstar = 0xFFFFFFFFu - (unsigned)(k & 0xFFFFFFFFULL);
        int lab = (int)targets[b * OO * 5 + lane * 5 + 4];
        g_ovr[b * OO + lane] =
            ((unsigned long long)pstar << 16) | (unsigned)(lab | (lane << 8));
    }
}

// ============ K3: fused match + CE + loc loss, grid (TC, BB) x 128 ============
__global__ __launch_bounds__(128) void k_ce(
    const float4* __restrict__ loc4, const float* __restrict__ conf,
    const float4* __restrict__ priors4, const float* __restrict__ targets)
{
    const int b = blockIdx.y, t = blockIdx.x;
    const int tid = threadIdx.x, lane = tid & 31, wid = tid >> 5;

    __shared__ float4 s_t4[OO];
    __shared__ float  s_area[OO], s_lab[OO];
    __shared__ unsigned long long s_ovr[OO];
    __shared__ float  s_conf[4][32 * CC];
    __shared__ float s_rll[4], s_rcep[4];
    __shared__ int   s_rnp[4];

    if (tid < OO * 5) {
        int o = tid / 5, j = tid % 5;
        float v = targets[b * OO * 5 + tid];
        if (j < 4) ((float*)s_t4)[o * 4 + j] = v;
        else       s_lab[o] = v;
    }
    if (tid < OO) s_ovr[tid] = g_ovr[b * OO + tid];
    __syncthreads();
    if (tid < OO) {
        float4 tt = s_t4[tid];
        s_area[tid] = (tt.z - tt.x) * (tt.w - tt.y);
    }
    __syncthreads();

    const int wt0 = t * TPC, wt1 = min(wt0 + TPC, NTILES);
    float ll = 0.0f, cep = 0.0f; int np = 0;

    for (int wt = wt0 + wid; wt < wt1; wt += 4) {
        int p32 = wt * 32;
        const float* cb = conf + ((size_t)b * PP + p32) * CC;
        float* sc = s_conf[wid];
        if (p32 + 32 <= PP) {
            #pragma unroll
            for (int i = 0; i < CC; i++) sc[i * 32 + lane] = cb[i * 32 + lane];
        } else {
            int lim = (PP - p32) * CC;
            #pragma unroll
            for (int i = 0; i < CC; i++) {
                int j = i * 32 + lane;
                sc[j] = cb[j < lim ? j : 0];
            }
        }
        __syncwarp();
        int n = min(32, PP - p32);
        bool actv = lane < n;
        int p = p32 + (actv ? lane : 0);

        // inline match (identical comparator to the two-pass version)
        int ct = 0, bti = 0;
        float4 pq;
        if (actv) {
            pq = priors4[p];
            float hw = pq.z * 0.5f, hh = pq.w * 0.5f;
            float px0 = pq.x - hw, py0 = pq.y - hh;
            float px1 = pq.x + hw, py1 = pq.y + hh;
            float pa = pq.z * pq.w;
            float bto = -1.0f;
            #pragma unroll
            for (int o = 0; o < OO; o++) {
                float4 tt = s_t4[o];               // LDS.128 broadcast
                float ar = s_area[o];
                float iw = fminf(tt.z, px1) - fmaxf(tt.x, px0);
                float ih = fminf(tt.w, py1) - fmaxf(tt.y, py0);
                iw = fmaxf(iw, 0.0f); ih = fmaxf(ih, 0.0f);
                float inter = iw * ih;
                float iou = __fdividef(inter, ar + pa - inter);
                if (iou > bto) { bto = iou; bti = o; }
            }
            ct = (bto >= THRESH) ? (int)s_lab[bti] : 0;
        }
        // override check: does any best-prior land in this tile?
        bool h = false;
        if (lane < OO) {
            unsigned ps = (unsigned)(s_ovr[lane] >> 16);
            h = (ps >> 5) == (unsigned)wt;
        }
        unsigned hb = __ballot_sync(0xffffffffu, h);
        if (hb && actv) {
            #pragma unroll
            for (int o = 0; o < OO; o++) {          // ascending: last-wins
                unsigned long long e = s_ovr[o];
                if ((unsigned)(e >> 16) == (unsigned)p) {
                    ct = (int)(e & 0xFFu); bti = (int)((e >> 8) & 0xFFu);
                }
            }
        }

        if (actv) {
            const float* row = sc + lane * CC;     // stride 21: conflict-free
            float s0 = 0.0f, s1 = 0.0f;
            #pragma unroll
            for (int c = 0; c < CC - 1; c += 2) {
                s0 += __expf(row[c]);
                s1 += __expf(row[c + 1]);
            }
            s0 += __expf(row[CC - 1]);
            float lse = __logf(s0 + s1);
            float ce = lse - row[ct];
            bool pos = ct > 0;
            g_mined[(size_t)b * PP + p] = pos ? 0u : __float_as_uint(fmaxf(ce, 0.0f));
            if (pos) {
                cep += ce; np++;
                float4 ld = loc4[(size_t)b * PP + p];
                float4 tt = s_t4[bti];
                float gx = __fdividef((tt.x + tt.z) * 0.5f - pq.x, VAR0 * pq.z);
                float gy = __fdividef((tt.y + tt.w) * 0.5f - pq.y, VAR0 * pq.w);
                float gw = __logf(__fdividef(tt.z - tt.x, pq.z)) * (1.0f / VAR1);
                float gh = __logf(__fdividef(tt.w - tt.y, pq.w)) * (1.0f / VAR1);
                ll += sl1(ld.x - gx) + sl1(ld.y - gy) +
                      sl1(ld.z - gw) + sl1(ld.w - gh);
            }
        }
        __syncwarp();
    }

    ll = warp_red_f(ll); cep = warp_red_f(cep); np = warp_red_i(np);
    if (lane == 0) { s_rll[wid] = ll; s_rcep[wid] = cep; s_rnp[wid] = np; }
    __syncthreads();
    if (tid == 0) {
        float a = 0.0f, c = 0.0f; int nn = 0;
        #pragma unroll
        for (int w = 0; w < 4; w++) { a += s_rll[w]; c += s_rcep[w]; nn += s_rnp[w]; }
        g_pll[b * TC + t] = a; g_pcep[b * TC + t] = c; g_pnp[b * TC + t] = nn;
    }
}

// ============ K4: 11-bit cut select, grid BB x 512 ============
__global__ __launch_bounds__(512, 1) void k_select()
{
    const int b = blockIdx.x;
    const int tid = threadIdx.x, lane = tid & 31, wid = tid >> 5;
    __shared__ unsigned s_hist[2048];
    __shared__ unsigned s_part[512];
    __shared__ float s_r[16];
    __shared__ float s_sgt;
    __shared__ int sh_kk;
    __shared__ int s_cctr;
    __shared__ unsigned sh_cut;             // 11-bit cut digit
    __shared__ unsigned sh_pref, sh_pmask;
    __shared__ float s_llT, s_cepT, s_negT;
    __shared__ int s_npT;

    if (wid == 0) {
        float a = (lane < TC) ? g_pll[b * TC + lane] : 0.0f;
        float c = (lane < TC) ? g_pcep[b * TC + lane] : 0.0f;
        int   n = (lane < TC) ? g_pnp[b * TC + lane] : 0;
        a = warp_red_f(a); c = warp_red_f(c); n = warp_red_i(n);
        if (lane == 0) {
            s_llT = a; s_cepT = c; s_npT = n;
            int k = NEGPOS * n; if (k > PP - 1) k = PP - 1;
            sh_kk = k;
            s_negT = 0.0f; s_sgt = 0.0f; s_cctr = 0;
        }
    }
    #pragma unroll
    for (int j = 0; j < 4; j++) s_hist[tid + j * 512] = 0u;
    __syncthreads();

    if (sh_kk > 0) {
        const unsigned* mined = g_mined + (size_t)b * PP;
        unsigned* cand = g_cand + (size_t)b * PP;

        // ---- scan 1: 2048-bin histogram of top-11 bits (MLP-8) ----
        for (int base = 0; base < PP; base += 512 * 8) {
            unsigned xx[8];
            #pragma unroll
            for (int j = 0; j < 8; j++) {
                int p = base + j * 512 + tid;
                xx[j] = (p < PP) ? mined[p] : 0xFFFFFFFFu;   // sentinel: no bin
            }
            #pragma unroll
            for (int j = 0; j < 8; j++) {
                bool valid = xx[j] != 0xFFFFFFFFu;
                unsigned dig = xx[j] >> 20;                  // <= 0x7FF for valid
                unsigned ab = __ballot_sync(0xffffffffu, valid);
                if (valid) {
                    unsigned peers = __match_any_sync(ab, dig);
                    if ((peers & ((1u << lane) - 1)) == 0)
                        atomicAdd(&s_hist[dig], (unsigned)__popc(peers));
                }
            }
        }
        __syncthreads();

        // ---- block-collective 2048-bin cut finder ----
        {
            unsigned p0 = s_hist[tid * 4], p1 = s_hist[tid * 4 + 1];
            unsigned p2 = s_hist[tid * 4 + 2], p3 = s_hist[tid * 4 + 3];
            s_part[tid] = p0 + p1 + p2 + p3;
        }
        __syncthreads();
        if (wid == 0) {
            unsigned c16[16]; unsigned lsum = 0;
            #pragma unroll
            for (int j = 0; j < 16; j++) { c16[j] = s_part[lane * 16 + j]; lsum += c16[j]; }
            unsigned sfx = lsum;
            #pragma unroll
            for (int off = 1; off < 32; off <<= 1) {
                unsigned w = __shfl_down_sync(0xffffffffu, sfx, off);
                if (lane + off < 32) sfx += w;
            }
            int kk = sh_kk;
            unsigned bal = __ballot_sync(0xffffffffu, sfx >= (unsigned)kk);
            int L = 31 - __clz(bal);
            if (lane == L) {
                unsigned run = sfx - lsum;
                int q = 0;
                #pragma unroll
                for (int j = 15; j >= 0; j--) {
                    if (run + c16[j] >= (unsigned)kk) { q = L * 16 + j; break; }
                    run += c16[j];
                }
                int cut = 0;
                #pragma unroll
                for (int i = 3; i >= 0; i--) {
                    unsigned c = s_hist[q * 4 + i];
                    if (run + c >= (unsigned)kk) { cut = q * 4 + i; break; }
                    run += c;
                }
                sh_cut = (unsigned)cut;
                sh_kk = kk - (int)run;
                sh_pref = (unsigned)cut << 20;
                sh_pmask = 0xFFF00000u;
            }
        }
        __syncthreads();
        const unsigned cut = sh_cut;

        // ---- scan 2: sum top11>cut (deterministic), compact top11==cut ----
        float sgt = 0.0f;
        for (int base = 0; base < PP; base += 512 * 8) {
            unsigned xx[8];
            #pragma unroll
            for (int j = 0; j < 8; j++) {
                int p = base + j * 512 + tid;
                xx[j] = (p < PP) ? mined[p] : 0u;
            }
            #pragma unroll
            for (int j = 0; j < 8; j++) {
                int p = base + j * 512 + tid;
                unsigned x = xx[j];
                unsigned top = x >> 20;
                bool valid = p < PP;
                if (valid && top > cut) sgt += __uint_as_float(x);
                bool eq = valid && (top == cut);
                unsigned bal = __ballot_sync(0xffffffffu, eq);
                if (bal) {
                    int leader = __ffs(bal) - 1;
                    int basei = 0;
                    if (lane == leader) basei = atomicAdd(&s_cctr, __popc(bal));
                    basei = __shfl_sync(0xffffffffu, basei, leader);
                    if (eq) cand[basei + __popc(bal & ((1u << lane) - 1))] = x;
                }
            }
        }
        sgt = warp_red_f(sgt);
        if (lane == 0) s_r[wid] = sgt;
        __syncthreads();
        if (tid == 0) {
            float tot = 0.0f;
            #pragma unroll
            for (int w = 0; w < 16; w++) tot += s_r[w];
            s_sgt = tot;
        }
        __syncthreads();
        const int nc = s_cctr;

        // ---- small passes on candidates: bits [19:12], [11:4], [3:0] ----
        const int shifts[3] = {12, 4, 0};
        #pragma unroll
        for (int pi = 0; pi < 3; pi++) {
            int shift = shifts[pi];
            for (int i = tid; i < 256; i += 512) s_hist[i] = 0u;
            __syncthreads();
            unsigned pref = sh_pref, pmask = sh_pmask;
            for (int base = 0; base < nc; base += 512) {
                int p = base + tid;
                unsigned x = (p < nc) ? cand[p] : 0u;
                bool v = (p < nc) && ((x & pmask) == pref);
                unsigned ab = __ballot_sync(0xffffffffu, v);
                if (v) {
                    unsigned dig = (x >> shift) & 0xFFu;   // last pass: bits[3:0] ≤ 0xF
                    unsigned peers = __match_any_sync(ab, dig);
                    if ((peers & ((1u << lane) - 1)) == 0)
                        atomicAdd(&s_hist[dig], (unsigned)__popc(peers));
                }
            }
            __syncthreads();
            if (wid == 0) find_digit256(s_hist, lane, shift, &sh_kk, &sh_pref, &sh_pmask);
            __syncthreads();
        }

        unsigned vb = sh_pref;           // exact k-th largest value bits
        float s = 0.0f;
        for (int p = tid; p < nc; p += 512) {
            unsigned x = cand[p];
            if (x > vb) s += __uint_as_float(x);
        }
        s = warp_red_f(s);
        if (lane == 0) s_r[wid] = s;
        __syncthreads();
        if (tid == 0) {
            float tot = 0.0f;
            #pragma unroll
            for (int w = 0; w < 16; w++) tot += s_r[w];
            s_negT = s_sgt + tot + __uint_as_float(vb) * (float)sh_kk;
        }
        __syncthreads();
    }

    if (tid == 0) {
        g_ll[b] = s_llT;
        g_lc[b] = s_cepT + s_negT;
        g_np[b] = s_npT;
    }
}

// ============ K5: finalize ============
__global__ void mb_fin(float* __restrict__ out) {
    const int t = threadIdx.x;   // 128 threads
    const int lane = t & 31, wid = t >> 5;
    __shared__ float s_a[4], s_b[4];
    __shared__ int s_n[4];
    float ll = g_ll[t], lc = g_lc[t];
    int np = g_np[t];
    ll = warp_red_f(ll); lc = warp_red_f(lc); np = warp_red_i(np);
    if (lane == 0) { s_a[wid] = ll; s_b[wid] = lc; s_n[wid] = np; }
    __syncthreads();
    if (t == 0) {
        float llT = 0.0f, lcT = 0.0f; int npT = 0;
        for (int w = 0; w < 4; w++) { llT += s_a[w]; lcT += s_b[w]; npT += s_n[w]; }
        float N = (npT > 0) ? (float)npT : (float)BB;
        out[0] = llT / N;
        out[1] = lcT / N;
    }
}

extern "C" void kernel_launch(void* const* d_in, const int* in_sizes, int n_in,
                              void* d_out, int out_size) {
    const float4* loc4    = (const float4*)d_in[0];   // [B,P,4]
    const float*  conf    = (const float*)d_in[1];    // [B,P,21]
    const float4* priors4 = (const float4*)d_in[2];   // [P,4]
    const float*  targets = (const float*)d_in[3];    // [B,16,5]
    float* out = (float*)d_out;

    k_best<<<dim3(TM, BB), 128>>>(priors4, targets);
    k_override<<<BB, 32>>>(targets);
    k_ce<<<dim3(TC, BB), 128>>>(loc4, conf, priors4, targets);
    k_select<<<BB, 512>>>();
    mb_fin<<<1, 128>>>(out);
}